// round 7
// baseline (speedup 1.0000x reference)
#include <cuda_runtime.h>
#include <cuda_bf16.h>
#include <stdint.h>

// ============================================================================
// TitansMACMemory: B=8192, H=4096, M=64
//   z = token @ [W1^T | W2]  -> h = gelu(z), tw2
//   C = W2^T W2 ; dz = c*gelu'(z)*(h@C - tw2),  c = 2/(B*H)
//   U = token^T @ [h | dz]   -> thth = U[:, :64], g1^T = U[:, 64:]
//   g2 = c*(W2 @ (h^T h) - thth)
//   W1n = .99 W1 + .9 m1 - es*g1 ; W2n = .99 W2 + .9 m2 - es*g2 ; es=e^log_eta*gate
//   out = gelu(token @ W1n^T) @ W2n^T      (bf16 hi/lo split, 3-pass MMA)
// U partial-reduce fused into k4a/k4b; k4a uses a smem transpose tile so both
// the strided-U read and the W1-layout write stay fully coalesced.
// ============================================================================

#define B_SZ 8192
#define H_SZ 4096
#define C2F  (2.0f / (8192.0f * 4096.0f))
#define LDS  72   // smem row stride (bf16): 144B -> +4-bank shift per row
#define UPS  (4096 * 128)   // one U-partial slice

// ---------------- device scratch (no allocations allowed) -------------------
__device__ __nv_bfloat16 g_Wcat[128 * 4096];     // [n][k]; n<64: W1[n][k], n>=64: W2[k][n-64]
__device__ float g_h  [B_SZ * 64];
__device__ float g_dz [B_SZ * 64];
__device__ float g_gram_part[64 * 4096];
__device__ float g_C  [64 * 64];
__device__ float g_hTh[64 * 64];
__device__ float g_Upart[8 * UPS];
__device__ __nv_bfloat16 g_W1hi[64 * 4096], g_W1lo[64 * 4096];   // [m][k]
__device__ __nv_bfloat16 g_W2hi[4096 * 64], g_W2lo[4096 * 64];   // [h][m]
__device__ __nv_bfloat16 g_h2hi[B_SZ * 64], g_h2lo[B_SZ * 64];   // [b][m]

// ---------------- helpers ----------------------------------------------------
__device__ __forceinline__ float gelu_f(float x) {
    return 0.5f * x * (1.0f + erff(x * 0.7071067811865475f));
}
__device__ __forceinline__ float gelu_g(float x) {
    float cdf = 0.5f * (1.0f + erff(x * 0.7071067811865475f));
    return cdf + x * 0.3989422804014327f * expf(-0.5f * x * x);
}
__device__ __forceinline__ void mma_bf16(float* c, uint32_t a0, uint32_t a1,
                                         uint32_t a2, uint32_t a3,
                                         uint32_t b0, uint32_t b1) {
    asm volatile(
        "mma.sync.aligned.m16n8k16.row.col.f32.bf16.bf16.f32 "
        "{%0,%1,%2,%3},{%4,%5,%6,%7},{%8,%9},{%0,%1,%2,%3};\n"
        : "+f"(c[0]), "+f"(c[1]), "+f"(c[2]), "+f"(c[3])
        : "r"(a0), "r"(a1), "r"(a2), "r"(a3), "r"(b0), "r"(b1));
}
__device__ __forceinline__ uint32_t ldu32(const __nv_bfloat16* p) {
    return *reinterpret_cast<const uint32_t*>(p);
}
__device__ __forceinline__ void st_bf2(__nv_bfloat16* p, float x, float y) {
    __nv_bfloat162 v = __floats2bfloat162_rn(x, y);
    *reinterpret_cast<__nv_bfloat162*>(p) = v;
}
__device__ __forceinline__ void split_st2(__nv_bfloat16* ph, __nv_bfloat16* pl,
                                          float x, float y) {
    __nv_bfloat16 hx = __float2bfloat16(x), hy = __float2bfloat16(y);
    __nv_bfloat162 hv; hv.x = hx; hv.y = hy;
    *reinterpret_cast<__nv_bfloat162*>(ph) = hv;
    __nv_bfloat162 lv;
    lv.x = __float2bfloat16(x - __bfloat162float(hx));
    lv.y = __float2bfloat16(y - __bfloat162float(hy));
    *reinterpret_cast<__nv_bfloat162*>(pl) = lv;
}

// ---------------- prep: Wcat (bf16) ------------------------------------------
__global__ void prep_kernel(const float* __restrict__ W1, const float* __restrict__ W2) {
    int idx = blockIdx.x * blockDim.x + threadIdx.x;   // 512*1024 = 524288 exact
    int n = idx >> 12, k = idx & 4095;
    float v = (n < 64) ? W1[n * 4096 + k] : W2[k * 64 + (n - 64)];
    g_Wcat[idx] = __float2bfloat16(v);
}

// ---------------- gram: X^T X for X = (rows x 64), 128-row chunks ------------
// use_h == 0 : X = external pointer (W2) ; use_h == 1 : X = g_h device symbol
__global__ void gram_part_kernel(const float* __restrict__ Xext, int use_h) {
    __shared__ float sx[128 * 64];
    const float* X = use_h ? g_h : Xext;
    int t = threadIdx.x;   // 1024
    const float4* src = reinterpret_cast<const float4*>(X + (size_t)blockIdx.x * 128 * 64);
    float4* dst = reinterpret_cast<float4*>(sx);
    dst[t] = src[t];
    dst[t + 1024] = src[t + 1024];
    __syncthreads();
#pragma unroll
    for (int i = 0; i < 4; i++) {
        int e = t + i * 1024;
        int j = e >> 6, m = e & 63;
        float s = 0.f;
#pragma unroll 8
        for (int k = 0; k < 128; k++) s += sx[k * 64 + j] * sx[k * 64 + m];
        g_gram_part[blockIdx.x * 4096 + e] = s;
    }
}
__global__ void gram_reduce_kernel(int S, int which) {
    int e = blockIdx.x * blockDim.x + threadIdx.x;  // 4*1024 = 4096
    float s = 0.f;
    for (int i = 0; i < S; i++) s += g_gram_part[i * 4096 + e];
    if (which == 0) g_C[e] = s; else g_hTh[e] = s;
}

// ---------------- K1: z/tw2 GEMM + fused h, dz epilogue ----------------------
// tile: 64 rows (b) x 128 cols; K=4096. smem: 50176 B (epilogue needs most).
__global__ void __launch_bounds__(256) k1_kernel(const float* __restrict__ token) {
    extern __shared__ unsigned char smem[];
    __nv_bfloat16* sA = reinterpret_cast<__nv_bfloat16*>(smem);                // [64][72]
    __nv_bfloat16* sB = reinterpret_cast<__nv_bfloat16*>(smem + 64 * LDS * 2); // [128][72]
    const int t = threadIdx.x, warp = t >> 5, lane = t & 31;
    const int gid = lane >> 2, tig = lane & 3;
    const int b0 = blockIdx.x * 64;
    const int m0 = (warp & 3) * 16, n0 = (warp >> 2) * 64;
    float acc[8][4];
#pragma unroll
    for (int i = 0; i < 8; i++)
#pragma unroll
        for (int j = 0; j < 4; j++) acc[i][j] = 0.f;

    float4 pa[4]; uint4 pb[4];
#pragma unroll
    for (int r = 0; r < 4; r++) {
        int q = r * 256 + t; int row = q >> 4, k = (q & 15) * 4;
        pa[r] = *reinterpret_cast<const float4*>(&token[(size_t)(b0 + row) * 4096 + k]);
    }
#pragma unroll
    for (int r = 0; r < 4; r++) {
        int q = r * 256 + t; int n = q >> 3, k = (q & 7) * 8;
        pb[r] = *reinterpret_cast<const uint4*>(&g_Wcat[(size_t)n * 4096 + k]);
    }
    for (int it = 0; it < 64; ++it) {
        __syncthreads();
#pragma unroll
        for (int r = 0; r < 4; r++) {
            int q = r * 256 + t; int row = q >> 4, k = (q & 15) * 4;
            st_bf2(&sA[row * LDS + k], pa[r].x, pa[r].y);
            st_bf2(&sA[row * LDS + k + 2], pa[r].z, pa[r].w);
        }
#pragma unroll
        for (int r = 0; r < 4; r++) {
            int q = r * 256 + t; int n = q >> 3, k = (q & 7) * 8;
            *reinterpret_cast<uint4*>(&sB[n * LDS + k]) = pb[r];
        }
        __syncthreads();
        if (it < 63) {
            int k0 = (it + 1) * 64;
#pragma unroll
            for (int r = 0; r < 4; r++) {
                int q = r * 256 + t; int row = q >> 4, k = (q & 15) * 4;
                pa[r] = *reinterpret_cast<const float4*>(&token[(size_t)(b0 + row) * 4096 + k0 + k]);
            }
#pragma unroll
            for (int r = 0; r < 4; r++) {
                int q = r * 256 + t; int n = q >> 3, k = (q & 7) * 8;
                pb[r] = *reinterpret_cast<const uint4*>(&g_Wcat[(size_t)n * 4096 + k0 + k]);
            }
        }
#pragma unroll
        for (int ka = 0; ka < 4; ka++) {
            int kk = ka * 16;
            uint32_t a0 = ldu32(&sA[(m0 + gid) * LDS + kk + tig * 2]);
            uint32_t a1 = ldu32(&sA[(m0 + gid + 8) * LDS + kk + tig * 2]);
            uint32_t a2 = ldu32(&sA[(m0 + gid) * LDS + kk + 8 + tig * 2]);
            uint32_t a3 = ldu32(&sA[(m0 + gid + 8) * LDS + kk + 8 + tig * 2]);
#pragma unroll
            for (int na = 0; na < 8; na++) {
                int nn = n0 + na * 8 + gid;
                uint32_t br0 = ldu32(&sB[nn * LDS + kk + tig * 2]);
                uint32_t br1 = ldu32(&sB[nn * LDS + kk + 8 + tig * 2]);
                mma_bf16(acc[na], a0, a1, a2, a3, br0, br1);
            }
        }
    }
    __syncthreads();
    // ---- epilogue: dump z tile, compute h / gelu' / dz ----
    float* zt = reinterpret_cast<float*>(smem);               // [64][132] f32
    const int LZ = 132;
    float* sC = reinterpret_cast<float*>(smem + 64 * LZ * 4); // [64][64] f32
#pragma unroll
    for (int na = 0; na < 8; na++) {
        int col = n0 + na * 8 + tig * 2;
        zt[(m0 + gid) * LZ + col]         = acc[na][0];
        zt[(m0 + gid) * LZ + col + 1]     = acc[na][1];
        zt[(m0 + gid + 8) * LZ + col]     = acc[na][2];
        zt[(m0 + gid + 8) * LZ + col + 1] = acc[na][3];
    }
    for (int i = t; i < 4096; i += 256) sC[i] = g_C[i];
    __syncthreads();
    int row = t >> 2, mb = (t & 3) * 16;
    float gp[16];
#pragma unroll
    for (int i = 0; i < 16; i++) {
        int m = mb + i;
        float z = zt[row * LZ + m];
        float h = gelu_f(z);
        gp[i] = gelu_g(z);
        zt[row * LZ + m] = h;
        g_h[(size_t)(b0 + row) * 64 + m] = h;
    }
    __syncthreads();
#pragma unroll
    for (int i = 0; i < 16; i++) {
        int m = mb + i;
        float hc = 0.f;
#pragma unroll 8
        for (int j = 0; j < 64; j++) hc += zt[row * LZ + j] * sC[j * 64 + m];
        float dz = C2F * gp[i] * (hc - zt[row * LZ + 64 + m]);
        g_dz[(size_t)(b0 + row) * 64 + m] = dz;
    }
}

// ---------------- K3: U = token^T @ [h|dz], split-K partials -----------------
// grid (64 h-tiles, 8 splits). tile 64(h) x 128(n), K=1024 per split.
__global__ void __launch_bounds__(256) k3_kernel(const float* __restrict__ token) {
    extern __shared__ unsigned char smem[];
    __nv_bfloat16* sA = reinterpret_cast<__nv_bfloat16*>(smem);                // [64 h][72]
    __nv_bfloat16* sB = reinterpret_cast<__nv_bfloat16*>(smem + 64 * LDS * 2); // [128 n][72]
    const int t = threadIdx.x, warp = t >> 5, lane = t & 31;
    const int gid = lane >> 2, tig = lane & 3;
    const int h0 = blockIdx.x * 64;
    const int bbase = blockIdx.y * 1024;
    const int m0 = (warp & 3) * 16, n0 = (warp >> 2) * 64;
    float acc[8][4];
#pragma unroll
    for (int i = 0; i < 8; i++)
#pragma unroll
        for (int j = 0; j < 4; j++) acc[i][j] = 0.f;

    float4 pa[4], pbh[4], pbd[4];
#pragma unroll
    for (int r = 0; r < 4; r++) {
        int q = r * 256 + t; int bk = q >> 4, i = (q & 15) * 4;
        pa[r]  = *reinterpret_cast<const float4*>(&token[(size_t)(bbase + bk) * 4096 + h0 + i]);
        pbh[r] = *reinterpret_cast<const float4*>(&g_h [(size_t)(bbase + bk) * 64 + i]);
        pbd[r] = *reinterpret_cast<const float4*>(&g_dz[(size_t)(bbase + bk) * 64 + i]);
    }
    for (int it = 0; it < 16; ++it) {
        __syncthreads();
#pragma unroll
        for (int r = 0; r < 4; r++) {
            int q = r * 256 + t; int bk = q >> 4, i = (q & 15) * 4;
            sA[(i + 0) * LDS + bk] = __float2bfloat16(pa[r].x);
            sA[(i + 1) * LDS + bk] = __float2bfloat16(pa[r].y);
            sA[(i + 2) * LDS + bk] = __float2bfloat16(pa[r].z);
            sA[(i + 3) * LDS + bk] = __float2bfloat16(pa[r].w);
            sB[(i + 0) * LDS + bk] = __float2bfloat16(pbh[r].x);
            sB[(i + 1) * LDS + bk] = __float2bfloat16(pbh[r].y);
            sB[(i + 2) * LDS + bk] = __float2bfloat16(pbh[r].z);
            sB[(i + 3) * LDS + bk] = __float2bfloat16(pbh[r].w);
            sB[(64 + i + 0) * LDS + bk] = __float2bfloat16(pbd[r].x);
            sB[(64 + i + 1) * LDS + bk] = __float2bfloat16(pbd[r].y);
            sB[(64 + i + 2) * LDS + bk] = __float2bfloat16(pbd[r].z);
            sB[(64 + i + 3) * LDS + bk] = __float2bfloat16(pbd[r].w);
        }
        __syncthreads();
        if (it < 15) {
            int bb = bbase + (it + 1) * 64;
#pragma unroll
            for (int r = 0; r < 4; r++) {
                int q = r * 256 + t; int bk = q >> 4, i = (q & 15) * 4;
                pa[r]  = *reinterpret_cast<const float4*>(&token[(size_t)(bb + bk) * 4096 + h0 + i]);
                pbh[r] = *reinterpret_cast<const float4*>(&g_h [(size_t)(bb + bk) * 64 + i]);
                pbd[r] = *reinterpret_cast<const float4*>(&g_dz[(size_t)(bb + bk) * 64 + i]);
            }
        }
#pragma unroll
        for (int ka = 0; ka < 4; ka++) {
            int kk = ka * 16;
            uint32_t a0 = ldu32(&sA[(m0 + gid) * LDS + kk + tig * 2]);
            uint32_t a1 = ldu32(&sA[(m0 + gid + 8) * LDS + kk + tig * 2]);
            uint32_t a2 = ldu32(&sA[(m0 + gid) * LDS + kk + 8 + tig * 2]);
            uint32_t a3 = ldu32(&sA[(m0 + gid + 8) * LDS + kk + 8 + tig * 2]);
#pragma unroll
            for (int na = 0; na < 8; na++) {
                int nn = n0 + na * 8 + gid;
                uint32_t br0 = ldu32(&sB[nn * LDS + kk + tig * 2]);
                uint32_t br1 = ldu32(&sB[nn * LDS + kk + 8 + tig * 2]);
                mma_bf16(acc[na], a0, a1, a2, a3, br0, br1);
            }
        }
    }
    float* up = &g_Upart[((size_t)blockIdx.y * 4096 + h0) * 128];
#pragma unroll
    for (int na = 0; na < 8; na++) {
        int col = n0 + na * 8 + tig * 2;
        *reinterpret_cast<float2*>(&up[(m0 + gid) * 128 + col])     = make_float2(acc[na][0], acc[na][1]);
        *reinterpret_cast<float2*>(&up[(m0 + gid + 8) * 128 + col]) = make_float2(acc[na][2], acc[na][3]);
    }
}

// ---------------- K4a: W1 update, U-reduce fused, smem-transposed ------------
// grid 64 blocks x 256 thr. Block owns k-tile [k0, k0+64) x all 64 m.
// Load phase walks m contiguously (coalesced U reads, fixed slice order);
// write phase walks k contiguously (coalesced W1/m1 reads + hi/lo writes).
__global__ void k4a_kernel(const float* __restrict__ W1, const float* __restrict__ m1,
                           const float* __restrict__ log_eta, const float* __restrict__ gate) {
    __shared__ float sU[64][65];                  // [k_local][m]
    const int t = threadIdx.x;
    const int k0 = blockIdx.x * 64;
    float es = expf(log_eta[0]) * gate[0];
#pragma unroll
    for (int r = 0; r < 16; r++) {                // 16*256 = 4096 elements
        int i = r * 256 + t;
        int kl = i >> 6, m = i & 63;
        size_t e = (size_t)(k0 + kl) * 128 + 64 + m;
        float s = 0.f;
#pragma unroll
        for (int p = 0; p < 8; p++) s += g_Upart[(size_t)p * UPS + e];
        sU[kl][m] = s;
    }
    __syncthreads();
#pragma unroll
    for (int r = 0; r < 16; r++) {
        int i = r * 256 + t;
        int m = i >> 6, kl = i & 63;
        int idx = m * 4096 + k0 + kl;
        float g1 = sU[kl][m];
        float x = 0.99f * W1[idx] + 0.9f * m1[idx] - es * g1;
        __nv_bfloat16 hi = __float2bfloat16(x);
        g_W1hi[idx] = hi;
        g_W1lo[idx] = __float2bfloat16(x - __bfloat162float(hi));
    }
}
// ---------------- K4b: W2 update (already coalesced: e = hrow*128+m) ---------
__global__ void k4b_kernel(const float* __restrict__ W2, const float* __restrict__ m2,
                           const float* __restrict__ log_eta, const float* __restrict__ gate) {
    __shared__ float sH[4096];
    int t = threadIdx.x;
    for (int i = t; i < 4096; i += 256) sH[i] = g_hTh[i];
    __syncthreads();
    int idx = blockIdx.x * 256 + t;               // 262144
    float es = expf(log_eta[0]) * gate[0];
    int hrow = idx >> 6, m = idx & 63;
    float wh = 0.f;
#pragma unroll 8
    for (int j = 0; j < 64; j++) wh += W2[(size_t)hrow * 64 + j] * sH[j * 64 + m];
    size_t e = (size_t)hrow * 128 + m;            // contiguous across the warp
    float thth = 0.f;
#pragma unroll
    for (int i = 0; i < 8; i++) thth += g_Upart[(size_t)i * UPS + e];
    float g2 = C2F * (wh - thth);
    float x = 0.99f * W2[idx] + 0.9f * m2[idx] - es * g2;
    __nv_bfloat16 hi = __float2bfloat16(x);
    g_W2hi[idx] = hi;
    g_W2lo[idx] = __float2bfloat16(x - __bfloat162float(hi));
}

// ---------------- K5a: z2 = token @ W1n^T (split), h2 = gelu(z2) -------------
// tile 64(b) x 64(m), K=4096, 3-pass hi/lo split. smem 36864 B.
__global__ void __launch_bounds__(256) k5a_kernel(const float* __restrict__ token) {
    extern __shared__ unsigned char smem[];
    __nv_bfloat16* sAh = reinterpret_cast<__nv_bfloat16*>(smem);          // [64][72]
    __nv_bfloat16* sAl = reinterpret_cast<__nv_bfloat16*>(smem + 9216);
    __nv_bfloat16* sBh = reinterpret_cast<__nv_bfloat16*>(smem + 18432);  // [64][72]
    __nv_bfloat16* sBl = reinterpret_cast<__nv_bfloat16*>(smem + 27648);
    const int t = threadIdx.x, warp = t >> 5, lane = t & 31;
    const int gid = lane >> 2, tig = lane & 3;
    const int b0 = blockIdx.x * 64;
    const int m0 = (warp & 3) * 16, n0 = (warp >> 2) * 32;
    float acc[4][4];
#pragma unroll
    for (int i = 0; i < 4; i++)
#pragma unroll
        for (int j = 0; j < 4; j++) acc[i][j] = 0.f;

    float4 pa[4]; uint4 pbh[2], pbl[2];
#pragma unroll
    for (int r = 0; r < 4; r++) {
        int q = r * 256 + t; int row = q >> 4, k = (q & 15) * 4;
        pa[r] = *reinterpret_cast<const float4*>(&token[(size_t)(b0 + row) * 4096 + k]);
    }
#pragma unroll
    for (int r = 0; r < 2; r++) {
        int q = r * 256 + t; int n = q >> 3, k = (q & 7) * 8;
        pbh[r] = *reinterpret_cast<const uint4*>(&g_W1hi[(size_t)n * 4096 + k]);
        pbl[r] = *reinterpret_cast<const uint4*>(&g_W1lo[(size_t)n * 4096 + k]);
    }
    for (int it = 0; it < 64; ++it) {
        __syncthreads();
#pragma unroll
        for (int r = 0; r < 4; r++) {
            int q = r * 256 + t; int row = q >> 4, k = (q & 15) * 4;
            split_st2(&sAh[row * LDS + k], &sAl[row * LDS + k], pa[r].x, pa[r].y);
            split_st2(&sAh[row * LDS + k + 2], &sAl[row * LDS + k + 2], pa[r].z, pa[r].w);
        }
#pragma unroll
        for (int r = 0; r < 2; r++) {
            int q = r * 256 + t; int n = q >> 3, k = (q & 7) * 8;
            *reinterpret_cast<uint4*>(&sBh[n * LDS + k]) = pbh[r];
            *reinterpret_cast<uint4*>(&sBl[n * LDS + k]) = pbl[r];
        }
        __syncthreads();
        if (it < 63) {
            int k0 = (it + 1) * 64;
#pragma unroll
            for (int r = 0; r < 4; r++) {
                int q = r * 256 + t; int row = q >> 4, k = (q & 15) * 4;
                pa[r] = *reinterpret_cast<const float4*>(&token[(size_t)(b0 + row) * 4096 + k0 + k]);
            }
#pragma unroll
            for (int r = 0; r < 2; r++) {
                int q = r * 256 + t; int n = q >> 3, k = (q & 7) * 8;
                pbh[r] = *reinterpret_cast<const uint4*>(&g_W1hi[(size_t)n * 4096 + k0 + k]);
                pbl[r] = *reinterpret_cast<const uint4*>(&g_W1lo[(size_t)n * 4096 + k0 + k]);
            }
        }
#pragma unroll
        for (int ka = 0; ka < 4; ka++) {
            int kk = ka * 16;
            uint32_t ah0 = ldu32(&sAh[(m0 + gid) * LDS + kk + tig * 2]);
            uint32_t ah1 = ldu32(&sAh[(m0 + gid + 8) * LDS + kk + tig * 2]);
            uint32_t ah2 = ldu32(&sAh[(m0 + gid) * LDS + kk + 8 + tig * 2]);
            uint32_t ah3 = ldu32(&sAh[(m0 + gid + 8) * LDS + kk + 8 + tig * 2]);
            uint32_t al0 = ldu32(&sAl[(m0 + gid) * LDS + kk + tig * 2]);
            uint32_t al1 = ldu32(&sAl[(m0 + gid + 8) * LDS + kk + tig * 2]);
            uint32_t al2 = ldu32(&sAl[(m0 + gid) * LDS + kk + 8 + tig * 2]);
            uint32_t al3 = ldu32(&sAl[(m0 + gid + 8) * LDS + kk + 8 + tig * 2]);
#pragma unroll
            for (int na = 0; na < 4; na++) {
                int nn = n0 + na * 8 + gid;
                uint32_t bh0 = ldu32(&sBh[nn * LDS + kk + tig * 2]);
                uint32_t bh1 = ldu32(&sBh[nn * LDS + kk + 8 + tig * 2]);
                uint32_t bl0 = ldu32(&sBl[nn * LDS + kk + tig * 2]);
                uint32_t bl1 = ldu32(&sBl[nn * LDS + kk + 8 + tig * 2]);
                mma_bf16(acc[na], ah0, ah1, ah2, ah3, bh0, bh1);
                mma_bf16(acc[na], ah0, ah1, ah2, ah3, bl0, bl1);
                mma_bf16(acc[na], al0, al1, al2, al3, bh0, bh1);
            }
        }
    }
    // epilogue: h2 = gelu(z2), split hi/lo, store
#pragma unroll
    for (int na = 0; na < 4; na++) {
        int col = n0 + na * 8 + tig * 2;
        {
            float v0 = gelu_f(acc[na][0]), v1 = gelu_f(acc[na][1]);
            size_t o = (size_t)(b0 + m0 + gid) * 64 + col;
            split_st2(&g_h2hi[o], &g_h2lo[o], v0, v1);
        }
        {
            float v2 = gelu_f(acc[na][2]), v3 = gelu_f(acc[na][3]);
            size_t o = (size_t)(b0 + m0 + gid + 8) * 64 + col;
            split_st2(&g_h2hi[o], &g_h2lo[o], v2, v3);
        }
    }
}

// ---------------- K5b: out = h2 @ W2n^T (split), write f32 -------------------
// grid (32 n-tiles, 64 b-tiles). tile 128(b) x 128(n), K=64. smem 73728 B.
__global__ void __launch_bounds__(256) k5b_kernel(float* __restrict__ out) {
    extern __shared__ unsigned char smem[];
    __nv_bfloat16* sAh = reinterpret_cast<__nv_bfloat16*>(smem);           // [128][72]
    __nv_bfloat16* sAl = reinterpret_cast<__nv_bfloat16*>(smem + 18432);
    __nv_bfloat16* sBh = reinterpret_cast<__nv_bfloat16*>(smem + 36864);   // [128][72]
    __nv_bfloat16* sBl = reinterpret_cast<__nv_bfloat16*>(smem + 55296);
    const int t = threadIdx.x, warp = t >> 5, lane = t & 31;
    const int gid = lane >> 2, tig = lane & 3;
    const int n0 = blockIdx.x * 128;
    const int b0 = blockIdx.y * 128;
#pragma unroll
    for (int r = 0; r < 4; r++) {
        int q = r * 256 + t; int row = q >> 3, k = (q & 7) * 8;
        *reinterpret_cast<uint4*>(&sAh[row * LDS + k]) =
            *reinterpret_cast<const uint4*>(&g_h2hi[(size_t)(b0 + row) * 64 + k]);
        *reinterpret_cast<uint4*>(&sAl[row * LDS + k]) =
            *reinterpret_cast<const uint4*>(&g_h2lo[(size_t)(b0 + row) * 64 + k]);
        *reinterpret_cast<uint4*>(&sBh[row * LDS + k]) =
            *reinterpret_cast<const uint4*>(&g_W2hi[(size_t)(n0 + row) * 64 + k]);
        *reinterpret_cast<uint4*>(&sBl[row * LDS + k]) =
            *reinterpret_cast<const uint4*>(&g_W2lo[(size_t)(n0 + row) * 64 + k]);
    }
    __syncthreads();
    const int m0 = warp * 16;
    float acc[16][4];
#pragma unroll
    for (int i = 0; i < 16; i++)
#pragma unroll
        for (int j = 0; j < 4; j++) acc[i][j] = 0.f;
#pragma unroll
    for (int ka = 0; ka < 4; ka++) {
        int kk = ka * 16;
        uint32_t ah0 = ldu32(&sAh[(m0 + gid) * LDS + kk + tig * 2]);
        uint32_t ah1 = ldu32(&sAh[(m0 + gid + 8) * LDS + kk + tig * 2]);
        uint32_t ah2 = ldu32(&sAh[(m0 + gid) * LDS + kk + 8 + tig * 2]);
        uint32_t ah3 = ldu32(&sAh[(m0 + gid + 8) * LDS + kk + 8 + tig * 2]);
        uint32_t al0 = ldu32(&sAl[(m0 + gid) * LDS + kk + tig * 2]);
        uint32_t al1 = ldu32(&sAl[(m0 + gid + 8) * LDS + kk + tig * 2]);
        uint32_t al2 = ldu32(&sAl[(m0 + gid) * LDS + kk + 8 + tig * 2]);
        uint32_t al3 = ldu32(&sAl[(m0 + gid + 8) * LDS + kk + 8 + tig * 2]);
#pragma unroll
        for (int na = 0; na < 16; na++) {
            int nn = na * 8 + gid;
            uint32_t bh0 = ldu32(&sBh[nn * LDS + kk + tig * 2]);
            uint32_t bh1 = ldu32(&sBh[nn * LDS + kk + 8 + tig * 2]);
            uint32_t bl0 = ldu32(&sBl[nn * LDS + kk + tig * 2]);
            uint32_t bl1 = ldu32(&sBl[nn * LDS + kk + 8 + tig * 2]);
            mma_bf16(acc[na], ah0, ah1, ah2, ah3, bh0, bh1);
            mma_bf16(acc[na], ah0, ah1, ah2, ah3, bl0, bl1);
            mma_bf16(acc[na], al0, al1, al2, al3, bh0, bh1);
        }
    }
#pragma unroll
    for (int na = 0; na < 16; na++) {
        int col = n0 + na * 8 + tig * 2;
        *reinterpret_cast<float2*>(&out[(size_t)(b0 + m0 + gid) * 4096 + col]) =
            make_float2(acc[na][0], acc[na][1]);
        *reinterpret_cast<float2*>(&out[(size_t)(b0 + m0 + gid + 8) * 4096 + col]) =
            make_float2(acc[na][2], acc[na][3]);
    }
}

// ---------------- launch ------------------------------------------------------
extern "C" void kernel_launch(void* const* d_in, const int* in_sizes, int n_in,
                              void* d_out, int out_size) {
    const float* token   = (const float*)d_in[0];
    const float* W1      = (const float*)d_in[1];
    const float* W2      = (const float*)d_in[2];
    const float* m1      = (const float*)d_in[3];
    const float* m2      = (const float*)d_in[4];
    const float* log_eta = (const float*)d_in[5];
    const float* gate    = (const float*)d_in[6];
    float* out = (float*)d_out;

    cudaFuncSetAttribute(k1_kernel,  cudaFuncAttributeMaxDynamicSharedMemorySize, 50176);
    cudaFuncSetAttribute(k5b_kernel, cudaFuncAttributeMaxDynamicSharedMemorySize, 73728);

    prep_kernel<<<512, 1024>>>(W1, W2);
    gram_part_kernel<<<32, 1024>>>(W2, 0);            // partials of W2^T W2
    gram_reduce_kernel<<<4, 1024>>>(32, 0);           // -> g_C
    k1_kernel<<<128, 256, 50176>>>(token);            // h, dz
    gram_part_kernel<<<64, 1024>>>(nullptr, 1);       // partials of h^T h (reads g_h)
    gram_reduce_kernel<<<4, 1024>>>(64, 1);           // -> g_hTh
    k3_kernel<<<dim3(64, 8), 256, 27648>>>(token);    // U partials
    k4a_kernel<<<64, 256>>>(W1, m1, log_eta, gate);   // U-reduce fused, transposed tile
    k4b_kernel<<<1024, 256>>>(W2, m2, log_eta, gate); // U-reduce + g2 fused
    k5a_kernel<<<128, 256, 36864>>>(token);           // h2 hi/lo
    k5b_kernel<<<dim3(32, 64), 256, 73728>>>(out);    // out f32
}